// round 12
// baseline (speedup 1.0000x reference)
#include <cuda_runtime.h>
#include <cuda_bf16.h>
#include <cuda_fp16.h>
#include <cstdint>
#include <cstddef>

// ============================================================================
// AutoregressiveGRU on GB300 — sm_103 base target, HMMA mma.sync.
//
// Mixed-precision 2-term scheme:
//   acc  += fp16(h) * fp16(W)                    (m16n8k16, 2 MMAs per k32)
//   acc2 += e4m3(h*2^6) * e4m3((W-fp16(W))*2^21) (m16n8k32, 1 MMA per k32)
//   result = acc + acc2 * 2^-27
// Weight-residual error 2^-15; dominant error stays fp16 state rounding 2^-11.
// One fused GEMM [256,1024]x[1024,4096] per step (z|r|xh|uh packed per d).
//
// R12 vs R11 (near mma.sync instruction roofline, rt≈19cyc):
//  - lo term moved to fp8 m16n8k32: MMAs/SMSP/chunk 128 -> 96
//  - fp8 tiles at 80B/row stride (conflict-free ldmatrix, no swizzle XOR)
// ============================================================================

#define DD 1024
#define BATCH 256
#define TSTEPS 128
#define NPACK 4096

#define CTA_M 64
#define CTA_N 128
#define KC 64            // K per chunk
#define KCH 16           // 1024 / 64
#define STAGES 4
#define A16_B (CTA_M * 128)               // 8192   fp16 A tile
#define BH_B  (CTA_N * 128)               // 16384  fp16 B-hi tile
#define A8_B  (CTA_M * 80)                // 5120   fp8 A tile (64B data + pad)
#define B8_B  (CTA_N * 80)                // 10240  fp8 B-lo tile
#define OFF_A16 0
#define OFF_BH  (A16_B)                   // 8192
#define OFF_A8  (A16_B + BH_B)            // 24576
#define OFF_B8  (OFF_A8 + A8_B)           // 29696
#define STAGE_BYTES (A16_B + BH_B + A8_B + B8_B)    // 39936 (mult of 128)
#define SMEM_DYN (STAGES * STAGE_BYTES)             // 159744

#define SCALE_A8 64.0f                    // 2^6
#define SCALE_B8 2097152.0f               // 2^21
#define INV_SCALE (1.0f / 134217728.0f)   // 2^-27

// ---------------- device globals --------------------------------------------
__device__ __half g_Wmh[NPACK * DD];          // main weights hi (fp16)
__device__ __half g_W1h[NPACK * DD];          // step-1 weights hi
__device__ unsigned char g_Wml8[NPACK * DD];  // main residual (e4m3, x2^21)
__device__ unsigned char g_W1l8[NPACK * DD];  // step-1 residual
__device__ __half g_h16[2][BATCH * DD];       // fp16 state, ping-pong
__device__ unsigned char g_h8[2][BATCH * DD]; // e4m3 state (x2^6), ping-pong
__device__ float g_hstate[BATCH * DD];        // fp32 state (epilogue hold)
__device__ float g_bias[NPACK];

// ---------------- PTX helpers -----------------------------------------------
__device__ __forceinline__ uint32_t smem_u32(const void* p) {
    uint32_t a;
    asm("{ .reg .u64 t; cvta.to.shared.u64 t, %1; cvt.u32.u64 %0, t; }" : "=r"(a) : "l"(p));
    return a;
}
__device__ __forceinline__ void cp16(uint32_t dst, const void* src) {
    asm volatile("cp.async.cg.shared.global [%0], [%1], 16;" :: "r"(dst), "l"(src) : "memory");
}
__device__ __forceinline__ void cp_commit() {
    asm volatile("cp.async.commit_group;" ::: "memory");
}
template <int N>
__device__ __forceinline__ void cp_wait() {
    asm volatile("cp.async.wait_group %0;" :: "n"(N) : "memory");
}
__device__ __forceinline__ void ldsm_x4(uint32_t* r, uint32_t addr) {
    asm volatile("ldmatrix.sync.aligned.m8n8.x4.shared.b16 {%0,%1,%2,%3}, [%4];"
                 : "=r"(r[0]), "=r"(r[1]), "=r"(r[2]), "=r"(r[3]) : "r"(addr));
}
__device__ __forceinline__ void mma_f16(float* c, const uint32_t* a, uint32_t b0, uint32_t b1) {
    asm volatile("mma.sync.aligned.m16n8k16.row.col.f32.f16.f16.f32 "
                 "{%0,%1,%2,%3}, {%4,%5,%6,%7}, {%8,%9}, {%0,%1,%2,%3};"
                 : "+f"(c[0]), "+f"(c[1]), "+f"(c[2]), "+f"(c[3])
                 : "r"(a[0]), "r"(a[1]), "r"(a[2]), "r"(a[3]), "r"(b0), "r"(b1));
}
__device__ __forceinline__ void mma_f8(float* c, const uint32_t* a, uint32_t b0, uint32_t b1) {
    asm volatile("mma.sync.aligned.m16n8k32.row.col.f32.e4m3.e4m3.f32 "
                 "{%0,%1,%2,%3}, {%4,%5,%6,%7}, {%8,%9}, {%0,%1,%2,%3};"
                 : "+f"(c[0]), "+f"(c[1]), "+f"(c[2]), "+f"(c[3])
                 : "r"(a[0]), "r"(a[1]), "r"(a[2]), "r"(a[3]), "r"(b0), "r"(b1));
}
__device__ __forceinline__ unsigned char f32_to_e4m3(float v) {
    unsigned short t;
    asm("cvt.rn.satfinite.e4m3x2.f32 %0, %1, %2;" : "=h"(t) : "f"(0.0f), "f"(v));
    return (unsigned char)(t & 0xFF);
}

// ---------------- step kernel ------------------------------------------------
__global__ __launch_bounds__(512, 1) void gru_step_kernel(
    const __half* __restrict__ Whi, const unsigned char* __restrict__ Wlo8,
    const __half* __restrict__ h16_in, const unsigned char* __restrict__ h8_in,
    __half* __restrict__ h16_out, unsigned char* __restrict__ h8_out,
    float* __restrict__ hstate,
    const float* __restrict__ bias, float* __restrict__ out, int t)
{
    extern __shared__ __align__(128) char smem_raw[];
    const uint32_t sbase = smem_u32(smem_raw);
    const int tid = threadIdx.x;
    const int wid = tid >> 5, lane = tid & 31;
    const int ctan = blockIdx.x;   // 0..31
    const int ctam = blockIdx.y;   // 0..3

    const int wm = wid & 1;        // 0..1 : 32-row warp block
    const int wn = wid >> 1;       // 0..7 : 16-col warp block

    const __half* Ag = h16_in + (size_t)ctam * CTA_M * DD;
    const unsigned char* A8g = h8_in + (size_t)ctam * CTA_M * DD;
    const __half* Bhg = Whi + (size_t)ctan * CTA_N * DD;
    const unsigned char* B8g = Wlo8 + (size_t)ctan * CTA_N * DD;

    // part 0: A fp16 + A8 ; part 1: Bh ; part 2: Bl8.
    auto issue_part = [&](int slot, int k0, int part) {
        uint32_t base = sbase + (uint32_t)slot * STAGE_BYTES;
        if (part == 0) {
            {   // fp16 A: 64 rows x 8 segs = 512 -> 1/thread
                int row = tid >> 3, grp = tid & 7;
                uint32_t sw = (uint32_t)(row * 128) + (uint32_t)((grp ^ (row & 7)) << 4);
                cp16(base + OFF_A16 + sw, Ag + (size_t)row * DD + k0 + grp * 8);
            }
            if (tid < 256) {  // fp8 A: 64 rows x 4 segs = 256
                int row = tid >> 2, seg = tid & 3;
                cp16(base + OFF_A8 + (uint32_t)(row * 80 + seg * 16),
                     A8g + (size_t)row * DD + k0 + seg * 16);
            }
        } else if (part == 1) {
#pragma unroll
            for (int it = 0; it < 2; ++it) {   // fp16 Bh: 128 rows x 8 segs
                int idx = tid + it * 512;
                int row = idx >> 3, grp = idx & 7;
                uint32_t sw = (uint32_t)(row * 128) + (uint32_t)((grp ^ (row & 7)) << 4);
                cp16(base + OFF_BH + sw, Bhg + (size_t)row * DD + k0 + grp * 8);
            }
        } else {
            {   // fp8 Bl: 128 rows x 4 segs = 512 -> 1/thread
                int row = tid >> 2, seg = tid & 3;
                cp16(base + OFF_B8 + (uint32_t)(row * 80 + seg * 16),
                     B8g + (size_t)row * DD + k0 + seg * 16);
            }
        }
    };
    auto issue_chunk = [&](int slot, int k0) {
        issue_part(slot, k0, 0); issue_part(slot, k0, 1); issue_part(slot, k0, 2);
        cp_commit();
    };

    float acc[2][2][4], acc2[2][2][4];
#pragma unroll
    for (int i = 0; i < 2; ++i)
#pragma unroll
        for (int j = 0; j < 2; ++j)
#pragma unroll
            for (int k = 0; k < 4; ++k) { acc[i][j][k] = 0.0f; acc2[i][j][k] = 0.0f; }

    // prologue: chunks 0..2 in flight
    issue_chunk(0, 0);
    issue_chunk(1, KC);
    issue_chunk(2, 2 * KC);

    // per-lane fragment addressing
    const int arow = wm * 32 + (lane & 15);
    const int agl = (lane >> 4);
    const int brow = wn * 16 + (lane & 7) + ((lane >> 4) & 1) * 8;
    const int bgl = (lane >> 3) & 1;

    // double-buffered fragments
    uint32_t fa[2][2][4], fbh[2][4], fa8[2][2][4], fb8[2][4];

#define LDSM_A(b, mt, kk_) do {                                                      \
    int row_ = arow + (mt) * 16;                                                     \
    uint32_t off_ = (uint32_t)(row_ * 128) +                                         \
                    (uint32_t)(((((kk_) * 2) + agl) ^ (row_ & 7)) << 4);             \
    ldsm_x4(fa[b][mt], aB + off_);                                                   \
} while (0)
#define LDSM_BH(b, kk_) do {                                                         \
    uint32_t off_ = (uint32_t)(brow * 128) +                                         \
                    (uint32_t)(((((kk_) * 2) + bgl) ^ (brow & 7)) << 4);             \
    ldsm_x4(fbh[b], bhB + off_);                                                     \
} while (0)
#define LDSM_A8(b, mt, c_) do {                                                      \
    int row_ = arow + (mt) * 16;                                                     \
    uint32_t off_ = (uint32_t)(row_ * 80) + (uint32_t)((agl + 2 * (c_)) << 4);       \
    ldsm_x4(fa8[b][mt], a8B + off_);                                                 \
} while (0)
#define LDSM_B8(b, c_) do {                                                          \
    uint32_t off_ = (uint32_t)(brow * 80) + (uint32_t)((bgl + 2 * (c_)) << 4);       \
    ldsm_x4(fb8[b], b8B + off_);                                                     \
} while (0)

    // hi body: 4 fp16 MMAs (k16 subtile kkc from buf bc) + 3 LDSM for kkn->bn
#define HI_BODY(bc, bn, kkn, do_ld) do {                                             \
    if (do_ld) LDSM_A(bn, 0, kkn);                                                   \
    mma_f16(acc[0][0], fa[bc][0], fbh[bc][0], fbh[bc][1]);                           \
    mma_f16(acc[0][1], fa[bc][0], fbh[bc][2], fbh[bc][3]);                           \
    if (do_ld) LDSM_BH(bn, kkn);                                                     \
    mma_f16(acc[1][0], fa[bc][1], fbh[bc][0], fbh[bc][1]);                           \
    if (do_ld) LDSM_A(bn, 1, kkn);                                                   \
    mma_f16(acc[1][1], fa[bc][1], fbh[bc][2], fbh[bc][3]);                           \
} while (0)

    // lo body: 4 fp8 MMAs (k32 subtile c from buf bc) + 3 LDSM for cn->bn
#define LO_BODY(bc, bn, cn, do_ld) do {                                              \
    if (do_ld) LDSM_A8(bn, 0, cn);                                                   \
    mma_f8(acc2[0][0], fa8[bc][0], fb8[bc][0], fb8[bc][1]);                          \
    if (do_ld) LDSM_B8(bn, cn);                                                      \
    mma_f8(acc2[0][1], fa8[bc][0], fb8[bc][2], fb8[bc][3]);                          \
    if (do_ld) LDSM_A8(bn, 1, cn);                                                   \
    mma_f8(acc2[1][0], fa8[bc][1], fb8[bc][0], fb8[bc][1]);                          \
    mma_f8(acc2[1][1], fa8[bc][1], fb8[bc][2], fb8[bc][3]);                          \
} while (0)

    for (int i = 0; i < KCH; ++i) {
        cp_wait<2>();
        __syncthreads();
        uint32_t base = sbase + (uint32_t)(i & (STAGES - 1)) * STAGE_BYTES;
        const uint32_t aB = base + OFF_A16;
        const uint32_t bhB = base + OFF_BH;
        const uint32_t a8B = base + OFF_A8;
        const uint32_t b8B = base + OFF_B8;
        const int pf = i + 3;
        const int pslot = pf & (STAGES - 1);
        const int pk0 = pf * KC;
        const bool pfv = (pf < KCH);

        // preload kk=0 (hi) and c=0 (lo) into buffer 0
        LDSM_A(0, 0, 0); LDSM_BH(0, 0); LDSM_A(0, 1, 0);
        LDSM_A8(0, 0, 0); LDSM_B8(0, 0); LDSM_A8(0, 1, 0);

        HI_BODY(0, 1, 1, true);
        if (pfv) issue_part(pslot, pk0, 0);
        LO_BODY(0, 1, 1, true);
        if (pfv) issue_part(pslot, pk0, 1);
        HI_BODY(1, 0, 2, true);
        if (pfv) issue_part(pslot, pk0, 2);
        HI_BODY(0, 1, 3, true);
        cp_commit();
        HI_BODY(1, 0, 0, false);
        LO_BODY(1, 0, 0, false);
    }
#undef HI_BODY
#undef LO_BODY
#undef LDSM_A
#undef LDSM_BH
#undef LDSM_A8
#undef LDSM_B8

    // ---- epilogue through SMEM ----
    __syncthreads();
    float* es = (float*)smem_raw;   // 64 x 128 fp32 = 32 KB
    {
        const int r0 = wm * 32 + (lane >> 2);
        const int c0 = wn * 16 + (lane & 3) * 2;
#pragma unroll
        for (int mt = 0; mt < 2; ++mt)
#pragma unroll
            for (int nb = 0; nb < 2; ++nb) {
                int r = r0 + mt * 16, c = c0 + nb * 8;
                *(float2*)&es[r * 128 + c] =
                    make_float2(acc[mt][nb][0] + acc2[mt][nb][0] * INV_SCALE,
                                acc[mt][nb][1] + acc2[mt][nb][1] * INV_SCALE);
                *(float2*)&es[(r + 8) * 128 + c] =
                    make_float2(acc[mt][nb][2] + acc2[mt][nb][2] * INV_SCALE,
                                acc[mt][nb][3] + acc2[mt][nb][3] * INV_SCALE);
            }
    }
    __syncthreads();

#pragma unroll
    for (int p = 0; p < 4; ++p) {
        int linear = p * 512 + tid;              // 0..2047
        int m = linear >> 5;                     // 0..63
        int dloc = linear & 31;                  // 0..31
        float4 v = *(float4*)&es[m * 128 + dloc * 4];
        float4 bb = __ldg((const float4*)(bias + ctan * 128 + dloc * 4));
        float vz = v.x + bb.x;
        float vr = v.y + bb.y;
        float vh = v.z + bb.z;
        float vu = v.w + bb.w;
        float z = 1.0f / (1.0f + __expf(-vz));
        float r = 1.0f / (1.0f + __expf(-vr));
        float hh = tanhf(vh + r * vu);
        int gm = ctam * CTA_M + m;
        int d = ctan * 32 + dloc;
        size_t hidx = (size_t)gm * DD + d;
        float hold = hstate[hidx];
        float hn = z * hold + (1.0f - z) * hh;
        out[(size_t)gm * (TSTEPS * DD) + (size_t)t * DD + d] = hn;
        hstate[hidx] = hn;
        h16_out[hidx] = __float2half_rn(hn);
        h8_out[hidx] = f32_to_e4m3(hn * SCALE_A8);
    }
}

// ---------------- pack / init kernels ---------------------------------------
__global__ void pack_weights(const float* __restrict__ W, const float* __restrict__ U,
                             const float* __restrict__ b,
                             __half* __restrict__ Wmh, unsigned char* __restrict__ Wml8,
                             __half* __restrict__ W1h, unsigned char* __restrict__ W1l8,
                             float* __restrict__ bp)
{
    int idx = blockIdx.x * blockDim.x + threadIdx.x;
    if (idx >= NPACK * DD) return;
    int c = idx >> 10;          // packed column (d*4 + gate)
    int k = idx & 1023;
    int d = c >> 2, g = c & 3;
    const int TD = 3 * DD;
    float vm, v1;
    if (g == 0)      { float u = U[(size_t)k * TD + d];            vm = W[(size_t)k * TD + d] + u;            v1 = u; }
    else if (g == 1) { float u = U[(size_t)k * TD + DD + d];       vm = W[(size_t)k * TD + DD + d] + u;       v1 = u; }
    else if (g == 2) { vm = W[(size_t)k * TD + 2 * DD + d];        v1 = 0.0f; }
    else             { float u = U[(size_t)k * TD + 2 * DD + d];   vm = u;    v1 = u; }
    __half h1 = __float2half_rn(vm);
    Wmh[idx] = h1;
    {
        unsigned short t;
        asm("cvt.rn.satfinite.e4m3x2.f32 %0, %1, %2;"
            : "=h"(t) : "f"(0.0f), "f"((vm - __half2float(h1)) * SCALE_B8));
        Wml8[idx] = (unsigned char)(t & 0xFF);
    }
    __half h2 = __float2half_rn(v1);
    W1h[idx] = h2;
    {
        unsigned short t;
        asm("cvt.rn.satfinite.e4m3x2.f32 %0, %1, %2;"
            : "=h"(t) : "f"(0.0f), "f"((v1 - __half2float(h2)) * SCALE_B8));
        W1l8[idx] = (unsigned char)(t & 0xFF);
    }
    if (k == 0)
        bp[c] = (g == 0) ? b[d] : (g == 1) ? b[DD + d] : (g == 2) ? b[2 * DD + d] : 0.0f;
}

__global__ void init_h(const float* __restrict__ x,
                       __half* __restrict__ h16, unsigned char* __restrict__ h8,
                       float* __restrict__ hstate)
{
    int i = blockIdx.x * blockDim.x + threadIdx.x;
    if (i < BATCH * DD) {
        float v = x[i];
        h16[i] = __float2half_rn(v);
        unsigned short t;
        asm("cvt.rn.satfinite.e4m3x2.f32 %0, %1, %2;"
            : "=h"(t) : "f"(0.0f), "f"(v * SCALE_A8));
        h8[i] = (unsigned char)(t & 0xFF);
        hstate[i] = v;
    }
}

// ---------------- launch -----------------------------------------------------
extern "C" void kernel_launch(void* const* d_in, const int* in_sizes, int n_in,
                              void* d_out, int out_size)
{
    const float* x = (const float*)d_in[0];
    const float* W = (const float*)d_in[1];
    const float* U = (const float*)d_in[2];
    const float* b = (const float*)d_in[3];
    float* out = (float*)d_out;

    void *pWmh, *pWml8, *pW1h, *pW1l8, *pH16, *pH8, *pHst, *pBias;
    cudaGetSymbolAddress(&pWmh, g_Wmh);
    cudaGetSymbolAddress(&pWml8, g_Wml8);
    cudaGetSymbolAddress(&pW1h, g_W1h);
    cudaGetSymbolAddress(&pW1l8, g_W1l8);
    cudaGetSymbolAddress(&pH16, g_h16);
    cudaGetSymbolAddress(&pH8, g_h8);
    cudaGetSymbolAddress(&pHst, g_hstate);
    cudaGetSymbolAddress(&pBias, g_bias);
    __half* Wmh = (__half*)pWmh;
    unsigned char* Wml8 = (unsigned char*)pWml8;
    __half* W1h = (__half*)pW1h;
    unsigned char* W1l8 = (unsigned char*)pW1l8;
    __half* H16 = (__half*)pH16;               // [2][BATCH*DD]
    unsigned char* H8 = (unsigned char*)pH8;   // [2][BATCH*DD]
    float* Hst = (float*)pHst;
    float* Bias = (float*)pBias;

    cudaFuncSetAttribute(gru_step_kernel, cudaFuncAttributeMaxDynamicSharedMemorySize, SMEM_DYN);

    pack_weights<<<(NPACK * DD + 255) / 256, 256>>>(W, U, b, Wmh, Wml8, W1h, W1l8, Bias);
    init_h<<<(BATCH * DD + 255) / 256, 256>>>(x, H16, H8, Hst);

    dim3 grid(32, 4);
    for (int t = 0; t < TSTEPS; ++t) {
        const __half* wh = (t == 0) ? W1h : Wmh;
        const unsigned char* wl = (t == 0) ? W1l8 : Wml8;
        int bin = t & 1, bout = (t + 1) & 1;
        gru_step_kernel<<<grid, 512, SMEM_DYN>>>(
            wh, wl,
            H16 + (size_t)bin * (BATCH * DD), H8 + (size_t)bin * (BATCH * DD),
            H16 + (size_t)bout * (BATCH * DD), H8 + (size_t)bout * (BATCH * DD),
            Hst, Bias, out, t);
    }
    (void)in_sizes; (void)n_in; (void)out_size;
}

// round 13
// speedup vs baseline: 1.1675x; 1.1675x over previous
#include <cuda_runtime.h>
#include <cuda_bf16.h>
#include <cuda_fp16.h>
#include <cstdint>
#include <cstddef>

// ============================================================================
// AutoregressiveGRU on GB300 — sm_103 base target, HMMA mma.sync m16n8k16.
//
// fp16 2-term scheme: acc += Ah*Bh ; acc2 += Ah*(Bl*2048); res = acc+acc2/2048.
// One fused GEMM [256,1024]x[1024,4096] per step (z|r|xh|uh packed per d).
//
// R13: PERSISTENT kernel over all 128 steps (128 CTAs, 1/SM, co-resident)
//  - atomic grid barrier between steps (reset by init kernel each launch)
//  - next-step B (weights, barrier-independent) prefetched during tail iters
//  - only 3 small A loads on the post-barrier critical path
//  - dedicated epilogue smem region (no clash with prefetched stages)
// ============================================================================

#define DD 1024
#define BATCH 256
#define TSTEPS 128
#define NPACK 4096

#define CTA_M 64
#define CTA_N 128
#define KC 64            // K per chunk (64 fp16 = 128 B/row)
#define KCH 16           // 1024 / 64
#define STAGES 4
#define A_TILE_B (CTA_M * 128)            // 8192
#define B_TILE_B (CTA_N * 128)            // 16384
#define STAGE_BYTES (A_TILE_B + 2 * B_TILE_B)       // 40960
#define ES_BYTES (CTA_M * CTA_N * 4)                // 32768 epilogue scratch
#define SMEM_DYN (STAGES * STAGE_BYTES + ES_BYTES)  // 196608

// ---------------- device globals --------------------------------------------
__device__ __half g_Wmh[NPACK * DD];     // main weights hi
__device__ __half g_Wml[NPACK * DD];     // main weights (lo * 2048)
__device__ __half g_W1h[NPACK * DD];     // step-1 weights hi
__device__ __half g_W1l[NPACK * DD];     // step-1 weights (lo * 2048)
__device__ __half g_h16[2][BATCH * DD];  // fp16 state ping-pong
__device__ float g_hstate[BATCH * DD];   // fp32 state
__device__ float g_bias[NPACK];
__device__ unsigned g_bar;               // grid barrier counter (reset by init_h)

// ---------------- PTX helpers -----------------------------------------------
__device__ __forceinline__ uint32_t smem_u32(const void* p) {
    uint32_t a;
    asm("{ .reg .u64 t; cvta.to.shared.u64 t, %1; cvt.u32.u64 %0, t; }" : "=r"(a) : "l"(p));
    return a;
}
__device__ __forceinline__ void cp16(uint32_t dst, const void* src) {
    asm volatile("cp.async.cg.shared.global [%0], [%1], 16;" :: "r"(dst), "l"(src) : "memory");
}
__device__ __forceinline__ void cp_commit() {
    asm volatile("cp.async.commit_group;" ::: "memory");
}
template <int N>
__device__ __forceinline__ void cp_wait() {
    asm volatile("cp.async.wait_group %0;" :: "n"(N) : "memory");
}
__device__ __forceinline__ void ldsm_x4(uint32_t* r, uint32_t addr) {
    asm volatile("ldmatrix.sync.aligned.m8n8.x4.shared.b16 {%0,%1,%2,%3}, [%4];"
                 : "=r"(r[0]), "=r"(r[1]), "=r"(r[2]), "=r"(r[3]) : "r"(addr));
}
__device__ __forceinline__ void mma_f16(float* c, const uint32_t* a, uint32_t b0, uint32_t b1) {
    asm volatile("mma.sync.aligned.m16n8k16.row.col.f32.f16.f16.f32 "
                 "{%0,%1,%2,%3}, {%4,%5,%6,%7}, {%8,%9}, {%0,%1,%2,%3};"
                 : "+f"(c[0]), "+f"(c[1]), "+f"(c[2]), "+f"(c[3])
                 : "r"(a[0]), "r"(a[1]), "r"(a[2]), "r"(a[3]), "r"(b0), "r"(b1));
}

// ---------------- persistent kernel ------------------------------------------
__global__ __launch_bounds__(512, 1) void gru_persistent_kernel(
    const __half* __restrict__ Wmh, const __half* __restrict__ Wml,
    const __half* __restrict__ W1h, const __half* __restrict__ W1l,
    __half* __restrict__ h16,            // [2][BATCH*DD]
    float* __restrict__ hstate,
    const float* __restrict__ bias, float* __restrict__ out)
{
    extern __shared__ __align__(128) char smem_raw[];
    const uint32_t sbase = smem_u32(smem_raw);
    float* es = (float*)(smem_raw + STAGES * STAGE_BYTES);
    const int tid = threadIdx.x;
    const int wid = tid >> 5, lane = tid & 31;
    const int ctan = blockIdx.x;   // 0..31
    const int ctam = blockIdx.y;   // 0..3

    const int wm = wid & 1;        // 0..1 : 32-row warp block
    const int wn = wid >> 1;       // 0..7 : 16-col warp block

    // per-thread cp.async coords
    const int cprowA = tid >> 3, cpgrpA = tid & 7;
    const uint32_t cpswA = (uint32_t)(cprowA * 128) + (uint32_t)((cpgrpA ^ (cprowA & 7)) << 4);

    auto issue_A = [&](int slot, int k0, const __half* Ag) {
        cp16(sbase + (uint32_t)slot * STAGE_BYTES + cpswA,
             Ag + (size_t)cprowA * DD + k0 + cpgrpA * 8);
    };
    auto issue_Bh = [&](int slot, int k0, const __half* Bhg) {
        uint32_t tb = sbase + (uint32_t)slot * STAGE_BYTES + A_TILE_B;
#pragma unroll
        for (int it = 0; it < 2; ++it) {
            int idx = tid + it * 512;
            int row = idx >> 3, grp = idx & 7;
            uint32_t sw = (uint32_t)(row * 128) + (uint32_t)((grp ^ (row & 7)) << 4);
            cp16(tb + sw, Bhg + (size_t)row * DD + k0 + grp * 8);
        }
    };
    auto issue_Bl = [&](int slot, int k0, const __half* Blg) {
        uint32_t tb = sbase + (uint32_t)slot * STAGE_BYTES + A_TILE_B + B_TILE_B;
#pragma unroll
        for (int it = 0; it < 2; ++it) {
            int idx = tid + it * 512;
            int row = idx >> 3, grp = idx & 7;
            uint32_t sw = (uint32_t)(row * 128) + (uint32_t)((grp ^ (row & 7)) << 4);
            cp16(tb + sw, Blg + (size_t)row * DD + k0 + grp * 8);
        }
    };

    // fragment addressing
    const int arow = wm * 32 + (lane & 15);
    const int agl = (lane >> 4);
    const int brow = wn * 16 + (lane & 7) + ((lane >> 4) & 1) * 8;
    const int bgl = (lane >> 3) & 1;

    uint32_t fa[2][2][4], fbh[2][4], fbl[2][4];

#define LDSM_A(b, mt, kk_) do {                                                      \
    int row_ = arow + (mt) * 16;                                                     \
    uint32_t off_ = (uint32_t)(row_ * 128) +                                         \
                    (uint32_t)(((((kk_) * 2) + agl) ^ (row_ & 7)) << 4);             \
    ldsm_x4(fa[b][mt], aB + off_);                                                   \
} while (0)
#define LDSM_BH(b, kk_) do {                                                         \
    uint32_t off_ = (uint32_t)(brow * 128) +                                         \
                    (uint32_t)(((((kk_) * 2) + bgl) ^ (brow & 7)) << 4);             \
    ldsm_x4(fbh[b], bhB + off_);                                                     \
} while (0)
#define LDSM_BL(b, kk_) do {                                                         \
    uint32_t off_ = (uint32_t)(brow * 128) +                                         \
                    (uint32_t)(((((kk_) * 2) + bgl) ^ (brow & 7)) << 4);             \
    ldsm_x4(fbl[b], blB + off_);                                                     \
} while (0)
#define KK_BODY(bc, bn, kkn, do_ld) do {                                             \
    if (do_ld) LDSM_A(bn, 0, kkn);                                                   \
    mma_f16(acc[0][0],  fa[bc][0], fbh[bc][0], fbh[bc][1]);                          \
    mma_f16(acc[0][1],  fa[bc][0], fbh[bc][2], fbh[bc][3]);                          \
    if (do_ld) LDSM_BH(bn, kkn);                                                     \
    mma_f16(acc2[0][0], fa[bc][0], fbl[bc][0], fbl[bc][1]);                          \
    mma_f16(acc2[0][1], fa[bc][0], fbl[bc][2], fbl[bc][3]);                          \
    if (do_ld) LDSM_A(bn, 1, kkn);                                                   \
    mma_f16(acc[1][0],  fa[bc][1], fbh[bc][0], fbh[bc][1]);                          \
    mma_f16(acc[1][1],  fa[bc][1], fbh[bc][2], fbh[bc][3]);                          \
    if (do_ld) LDSM_BL(bn, kkn);                                                     \
    mma_f16(acc2[1][0], fa[bc][1], fbl[bc][0], fbl[bc][1]);                          \
    mma_f16(acc2[1][1], fa[bc][1], fbl[bc][2], fbl[bc][3]);                          \
} while (0)

    // ---- one-time prologue (t=0): B chunks 0..2 (W1), then A chunks 0..2 ----
    {
        const __half* Bhg0 = W1h + (size_t)ctan * CTA_N * DD;
        const __half* Blg0 = W1l + (size_t)ctan * CTA_N * DD;
        const __half* Ag0 = h16 + (size_t)ctam * CTA_M * DD;   // buffer 0
#pragma unroll
        for (int c = 0; c < 3; ++c) {
            issue_Bh(c, c * KC, Bhg0); issue_Bl(c, c * KC, Blg0); cp_commit();
        }
#pragma unroll
        for (int c = 0; c < 3; ++c) { issue_A(c, c * KC, Ag0); cp_commit(); }
    }

    const __half* BhgN = Wmh + (size_t)ctan * CTA_N * DD;   // steps >= 1
    const __half* BlgN = Wml + (size_t)ctan * CTA_N * DD;

    for (int t = 0; t < TSTEPS; ++t) {
        const int bin = t & 1, bout = bin ^ 1;
        const __half* Ag = h16 + (size_t)bin * (BATCH * DD) + (size_t)ctam * CTA_M * DD;
        const __half* Bhg = (t == 0) ? (W1h + (size_t)ctan * CTA_N * DD) : BhgN;
        const __half* Blg = (t == 0) ? (W1l + (size_t)ctan * CTA_N * DD) : BlgN;
        const bool have_next = (t + 1 < TSTEPS);

        float acc[2][2][4], acc2[2][2][4];
#pragma unroll
        for (int i = 0; i < 2; ++i)
#pragma unroll
            for (int j = 0; j < 2; ++j)
#pragma unroll
                for (int k = 0; k < 4; ++k) { acc[i][j][k] = 0.0f; acc2[i][j][k] = 0.0f; }

        for (int i = 0; i < KCH; ++i) {
            cp_wait<2>();
            __syncthreads();
            uint32_t base = sbase + (uint32_t)(i & (STAGES - 1)) * STAGE_BYTES;
            const uint32_t aB = base;
            const uint32_t bhB = base + A_TILE_B, blB = bhB + B_TILE_B;

            const int pf = i + 3;
            // mode 0: prefetch this step's chunk pf; mode 1: next step's B tile
            // (chunk pf-16 into slot pf-16) during tail iters; mode 2: nothing.
            int mode, pslot, pk0;
            if (pf < KCH) { mode = 0; pslot = pf & (STAGES - 1); pk0 = pf * KC; }
            else if (have_next && pf - KCH < 3) { mode = 1; pslot = pf - KCH; pk0 = (pf - KCH) * KC; }
            else { mode = 2; pslot = 0; pk0 = 0; }

            LDSM_A(0, 0, 0); LDSM_BH(0, 0); LDSM_A(0, 1, 0); LDSM_BL(0, 0);

            KK_BODY(0, 1, 1, true);
            if (mode == 0) issue_A(pslot, pk0, Ag);
            else if (mode == 1) issue_Bh(pslot, pk0, BhgN);
            KK_BODY(1, 0, 2, true);
            if (mode == 0) issue_Bh(pslot, pk0, Bhg);
            else if (mode == 1) issue_Bl(pslot, pk0, BlgN);
            KK_BODY(0, 1, 3, true);
            if (mode == 0) issue_Bl(pslot, pk0, Blg);
            cp_commit();
            KK_BODY(1, 0, 0, false);
        }

        // ---- epilogue (dedicated es region; no clash with prefetched B) ----
        {
            const float s = 1.0f / 2048.0f;
            const int r0 = wm * 32 + (lane >> 2);
            const int c0 = wn * 16 + (lane & 3) * 2;
#pragma unroll
            for (int mt = 0; mt < 2; ++mt)
#pragma unroll
                for (int nb = 0; nb < 2; ++nb) {
                    int r = r0 + mt * 16, c = c0 + nb * 8;
                    *(float2*)&es[r * 128 + c] =
                        make_float2(acc[mt][nb][0] + acc2[mt][nb][0] * s,
                                    acc[mt][nb][1] + acc2[mt][nb][1] * s);
                    *(float2*)&es[(r + 8) * 128 + c] =
                        make_float2(acc[mt][nb][2] + acc2[mt][nb][2] * s,
                                    acc[mt][nb][3] + acc2[mt][nb][3] * s);
                }
        }
        __syncthreads();

        __half* h16_out = h16 + (size_t)bout * (BATCH * DD);
#pragma unroll
        for (int p = 0; p < 4; ++p) {
            int linear = p * 512 + tid;              // 0..2047
            int m = linear >> 5;                     // 0..63
            int dloc = linear & 31;                  // 0..31
            float4 v = *(float4*)&es[m * 128 + dloc * 4];
            float4 bb = __ldg((const float4*)(bias + ctan * 128 + dloc * 4));
            float vz = v.x + bb.x;
            float vr = v.y + bb.y;
            float vh = v.z + bb.z;
            float vu = v.w + bb.w;
            float z = 1.0f / (1.0f + __expf(-vz));
            float r = 1.0f / (1.0f + __expf(-vr));
            float hh = tanhf(vh + r * vu);
            int gm = ctam * CTA_M + m;
            int d = ctan * 32 + dloc;
            size_t hidx = (size_t)gm * DD + d;
            float hold = hstate[hidx];
            float hn = z * hold + (1.0f - z) * hh;
            out[(size_t)gm * (TSTEPS * DD) + (size_t)t * DD + d] = hn;
            hstate[hidx] = hn;
            h16_out[hidx] = __float2half_rn(hn);
        }

        if (have_next) {
            // ---- grid barrier: all CTAs' h16_out visible before A loads ----
            __syncthreads();
            if (tid == 0) {
                __threadfence();
                atomicAdd(&g_bar, 1u);
                const unsigned target = (unsigned)(gridDim.x * gridDim.y) * (unsigned)(t + 1);
                while (*(volatile unsigned*)&g_bar < target) { }
                __threadfence();
            }
            __syncthreads();
            // post-barrier: only the small A tiles on the critical path
            const __half* AgN = h16 + (size_t)bout * (BATCH * DD) + (size_t)ctam * CTA_M * DD;
#pragma unroll
            for (int c = 0; c < 3; ++c) { issue_A(c, c * KC, AgN); cp_commit(); }
        }
    }
#undef KK_BODY
#undef LDSM_A
#undef LDSM_BH
#undef LDSM_BL
}

// ---------------- pack / init kernels ---------------------------------------
__global__ void pack_weights(const float* __restrict__ W, const float* __restrict__ U,
                             const float* __restrict__ b,
                             __half* __restrict__ Wmh, __half* __restrict__ Wml,
                             __half* __restrict__ W1h, __half* __restrict__ W1l,
                             float* __restrict__ bp)
{
    int idx = blockIdx.x * blockDim.x + threadIdx.x;
    if (idx >= NPACK * DD) return;
    int c = idx >> 10;          // packed column (d*4 + gate)
    int k = idx & 1023;
    int d = c >> 2, g = c & 3;
    const int TD = 3 * DD;
    float vm, v1;
    if (g == 0)      { float u = U[(size_t)k * TD + d];            vm = W[(size_t)k * TD + d] + u;            v1 = u; }
    else if (g == 1) { float u = U[(size_t)k * TD + DD + d];       vm = W[(size_t)k * TD + DD + d] + u;       v1 = u; }
    else if (g == 2) { vm = W[(size_t)k * TD + 2 * DD + d];        v1 = 0.0f; }
    else             { float u = U[(size_t)k * TD + 2 * DD + d];   vm = u;    v1 = u; }
    __half h1 = __float2half_rn(vm);
    Wmh[idx] = h1;
    Wml[idx] = __float2half_rn((vm - __half2float(h1)) * 2048.0f);
    __half h2 = __float2half_rn(v1);
    W1h[idx] = h2;
    W1l[idx] = __float2half_rn((v1 - __half2float(h2)) * 2048.0f);
    if (k == 0)
        bp[c] = (g == 0) ? b[d] : (g == 1) ? b[DD + d] : (g == 2) ? b[2 * DD + d] : 0.0f;
}

__global__ void init_h(const float* __restrict__ x,
                       __half* __restrict__ h16, float* __restrict__ hstate)
{
    int i = blockIdx.x * blockDim.x + threadIdx.x;
    if (i == 0) g_bar = 0u;     // reset grid barrier every launch (graph replays)
    if (i < BATCH * DD) {
        float v = x[i];
        h16[i] = __float2half_rn(v);
        hstate[i] = v;
    }
}

// ---------------- launch -----------------------------------------------------
extern "C" void kernel_launch(void* const* d_in, const int* in_sizes, int n_in,
                              void* d_out, int out_size)
{
    const float* x = (const float*)d_in[0];
    const float* W = (const float*)d_in[1];
    const float* U = (const float*)d_in[2];
    const float* b = (const float*)d_in[3];
    float* out = (float*)d_out;

    void *pWmh, *pWml, *pW1h, *pW1l, *pH16, *pHst, *pBias;
    cudaGetSymbolAddress(&pWmh, g_Wmh);
    cudaGetSymbolAddress(&pWml, g_Wml);
    cudaGetSymbolAddress(&pW1h, g_W1h);
    cudaGetSymbolAddress(&pW1l, g_W1l);
    cudaGetSymbolAddress(&pH16, g_h16);
    cudaGetSymbolAddress(&pHst, g_hstate);
    cudaGetSymbolAddress(&pBias, g_bias);
    __half* Wmh = (__half*)pWmh;
    __half* Wml = (__half*)pWml;
    __half* W1h = (__half*)pW1h;
    __half* W1l = (__half*)pW1l;
    __half* H16 = (__half*)pH16;     // [2][BATCH*DD]
    float* Hst = (float*)pHst;
    float* Bias = (float*)pBias;

    cudaFuncSetAttribute(gru_persistent_kernel,
                         cudaFuncAttributeMaxDynamicSharedMemorySize, SMEM_DYN);

    pack_weights<<<(NPACK * DD + 255) / 256, 256>>>(W, U, b, Wmh, Wml, W1h, W1l, Bias);
    init_h<<<(BATCH * DD + 255) / 256, 256>>>(x, H16, Hst);

    dim3 grid(32, 4);   // 128 CTAs <= 148 SMs, 1 CTA/SM: all co-resident
    gru_persistent_kernel<<<grid, 512, SMEM_DYN>>>(
        Wmh, Wml, W1h, W1l, H16, Hst, Bias, out);
    (void)in_sizes; (void)n_in; (void)out_size;
}